// round 1
// baseline (speedup 1.0000x reference)
#include <cuda_runtime.h>

// ---------------- problem constants / scratch ----------------
#define NMAX 50000
#define EMAX 1600000
#define FEAT 256
#define NHEAD 4

__device__ float g_h[(long long)NMAX * FEAT];      // 51.2 MB: h = x@W
__device__ float g_asrc[NMAX * NHEAD];
__device__ float g_adst[NMAX * NHEAD];
__device__ int   g_cnt[NMAX + 1];
__device__ int   g_off[NMAX + 2];
__device__ int   g_cur[NMAX + 1];
__device__ int   g_csr[EMAX + NMAX];               // src node per (dst-grouped) slot

// ---------------- 0: zero counters ----------------
__global__ void zero_kernel(int N) {
    int i = blockIdx.x * blockDim.x + threadIdx.x;
    if (i <= N) g_cnt[i] = 0;
}

// ---------------- 1: SGEMM  g_h = x @ W  (K = N = 256) ----------------
// BM=128, BN=128, BK=8, TM=TN=8, 256 threads
__global__ void gemm_kernel(const float* __restrict__ A, const float* __restrict__ B, int M) {
    constexpr int K = 256, NN = 256;
    constexpr int BM = 128, BN = 128, BK = 8, TM = 8, TN = 8;
    __shared__ __align__(16) float As[BK][BM];
    __shared__ __align__(16) float Bs[BK][BN];
    const int tid = threadIdx.x;
    const int tx = tid % (BN / TN);   // 0..15
    const int ty = tid / (BN / TN);   // 0..15
    const int row0 = blockIdx.y * BM;
    const int col0 = blockIdx.x * BN;

    const int a_r = tid >> 1;          // 0..127
    const int a_c = (tid & 1) * 4;     // 0 or 4
    const int b_r = tid >> 5;          // 0..7
    const int b_c = (tid & 31) * 4;    // 0..124

    float acc[TM][TN];
#pragma unroll
    for (int i = 0; i < TM; i++)
#pragma unroll
        for (int j = 0; j < TN; j++) acc[i][j] = 0.f;

    for (int k0 = 0; k0 < K; k0 += BK) {
        float4 av = make_float4(0.f, 0.f, 0.f, 0.f);
        int ar = row0 + a_r;
        if (ar < M) av = *(const float4*)&A[(long long)ar * K + k0 + a_c];
        As[a_c + 0][a_r] = av.x;
        As[a_c + 1][a_r] = av.y;
        As[a_c + 2][a_r] = av.z;
        As[a_c + 3][a_r] = av.w;
        *(float4*)&Bs[b_r][b_c] = *(const float4*)&B[(k0 + b_r) * NN + col0 + b_c];
        __syncthreads();
#pragma unroll
        for (int kk = 0; kk < BK; kk++) {
            float ra[TM], rb[TN];
            *(float4*)&ra[0] = *(const float4*)&As[kk][ty * TM];
            *(float4*)&ra[4] = *(const float4*)&As[kk][ty * TM + 4];
            *(float4*)&rb[0] = *(const float4*)&Bs[kk][tx * TN];
            *(float4*)&rb[4] = *(const float4*)&Bs[kk][tx * TN + 4];
#pragma unroll
            for (int i = 0; i < TM; i++)
#pragma unroll
                for (int j = 0; j < TN; j++) acc[i][j] += ra[i] * rb[j];
        }
        __syncthreads();
    }
#pragma unroll
    for (int i = 0; i < TM; i++) {
        int r = row0 + ty * TM + i;
        if (r < M) {
            *(float4*)&g_h[(long long)r * FEAT + col0 + tx * TN]     = *(float4*)&acc[i][0];
            *(float4*)&g_h[(long long)r * FEAT + col0 + tx * TN + 4] = *(float4*)&acc[i][4];
        }
    }
}

// ---------------- 2: per-node attention logits ----------------
// a_src[n,h] = sum_c h[n,h,c]*att_src[h,c] ; likewise a_dst. att flattened [h*64+c].
__global__ void logits_kernel(const float* __restrict__ att_src,
                              const float* __restrict__ att_dst, int N) {
    const int n = blockIdx.x;
    const int tid = threadIdx.x;  // 256
    const int lane = tid & 63;
    float hv = g_h[(long long)n * FEAT + tid];
    __shared__ float s1[256], s2[256];
    s1[tid] = hv * att_src[tid];
    s2[tid] = hv * att_dst[tid];
    __syncthreads();
#pragma unroll
    for (int st = 32; st >= 1; st >>= 1) {
        if (lane < st) { s1[tid] += s1[tid + st]; s2[tid] += s2[tid + st]; }
        __syncthreads();
    }
    if (lane == 0) {
        int head = tid >> 6;
        g_asrc[n * NHEAD + head] = s1[tid];
        g_adst[n * NHEAD + head] = s2[tid];
    }
}

// ---------------- 3: histogram of destinations (incl. self loops) ----------------
__global__ void count_kernel(const int* __restrict__ ei, int E, int N) {
    int i = blockIdx.x * blockDim.x + threadIdx.x;
    if (i >= E + N) return;
    int dst = (i < E) ? ei[E + i] : (i - E);
    atomicAdd(&g_cnt[dst], 1);
}

// ---------------- 4: single-block exclusive scan ----------------
__global__ void scan_kernel(int N) {
    __shared__ int sm[1024];
    __shared__ int carry;
    const int tid = threadIdx.x;
    if (tid == 0) carry = 0;
    __syncthreads();
    for (int base = 0; base < N; base += 1024) {
        int i = base + tid;
        int v = (i < N) ? g_cnt[i] : 0;
        sm[tid] = v;
        __syncthreads();
        for (int s = 1; s < 1024; s <<= 1) {
            int t = (tid >= s) ? sm[tid - s] : 0;
            __syncthreads();
            sm[tid] += t;
            __syncthreads();
        }
        int excl = sm[tid] - v + carry;
        if (i < N) { g_off[i] = excl; g_cur[i] = excl; }
        __syncthreads();
        if (tid == 1023) carry += sm[1023];
        __syncthreads();
    }
    if (tid == 0) g_off[N] = carry;
}

// ---------------- 5: scatter edges into dst-grouped CSR ----------------
__global__ void scatter_kernel(const int* __restrict__ ei, int E, int N) {
    int i = blockIdx.x * blockDim.x + threadIdx.x;
    if (i >= E + N) return;
    int src, dst;
    if (i < E) { src = ei[i]; dst = ei[E + i]; }
    else       { src = dst = i - E; }
    int slot = atomicAdd(&g_cur[dst], 1);
    g_csr[slot] = src;
}

// ---------------- 6: softmax + weighted aggregation + relu + L2 norm ----------------
// one block (256 threads) per destination node; thread = output channel
__global__ void aggregate_kernel(const float* __restrict__ bias,
                                 float* __restrict__ out, int N) {
    const int n = blockIdx.x;
    const int tid = threadIdx.x;
    const int head = tid >> 6;

    __shared__ __align__(16) float4 red4[256];
    __shared__ float red[256];
    __shared__ float m_sh[4], invd_sh[4];
    __shared__ int   s_sh[64];
    __shared__ float al_sh[4][64];

    const int beg = g_off[n];
    const int end = g_off[n + 1];
    const float4 ad4 = *(const float4*)&g_adst[n * NHEAD];

    // ---- pass 1: per-head max of leaky(e) ----
    float4 lmax = make_float4(-1e30f, -1e30f, -1e30f, -1e30f);
    for (int i = beg + tid; i < end; i += 256) {
        int s = g_csr[i];
        float4 as = *(const float4*)&g_asrc[s * NHEAD];
        float ex = as.x + ad4.x; ex = ex >= 0.f ? ex : 0.2f * ex;
        float ey = as.y + ad4.y; ey = ey >= 0.f ? ey : 0.2f * ey;
        float ez = as.z + ad4.z; ez = ez >= 0.f ? ez : 0.2f * ez;
        float ew = as.w + ad4.w; ew = ew >= 0.f ? ew : 0.2f * ew;
        lmax.x = fmaxf(lmax.x, ex); lmax.y = fmaxf(lmax.y, ey);
        lmax.z = fmaxf(lmax.z, ez); lmax.w = fmaxf(lmax.w, ew);
    }
    red4[tid] = lmax;
    __syncthreads();
#pragma unroll
    for (int st = 128; st >= 1; st >>= 1) {
        if (tid < st) {
            float4 a = red4[tid], b = red4[tid + st];
            a.x = fmaxf(a.x, b.x); a.y = fmaxf(a.y, b.y);
            a.z = fmaxf(a.z, b.z); a.w = fmaxf(a.w, b.w);
            red4[tid] = a;
        }
        __syncthreads();
    }
    if (tid == 0) {
        float4 m = red4[0];
        m_sh[0] = m.x; m_sh[1] = m.y; m_sh[2] = m.z; m_sh[3] = m.w;
    }
    __syncthreads();
    const float4 m4 = make_float4(m_sh[0], m_sh[1], m_sh[2], m_sh[3]);

    // ---- pass 2: per-head sum of exp ----
    float4 lsum = make_float4(0.f, 0.f, 0.f, 0.f);
    for (int i = beg + tid; i < end; i += 256) {
        int s = g_csr[i];
        float4 as = *(const float4*)&g_asrc[s * NHEAD];
        float ex = as.x + ad4.x; ex = ex >= 0.f ? ex : 0.2f * ex;
        float ey = as.y + ad4.y; ey = ey >= 0.f ? ey : 0.2f * ey;
        float ez = as.z + ad4.z; ez = ez >= 0.f ? ez : 0.2f * ez;
        float ew = as.w + ad4.w; ew = ew >= 0.f ? ew : 0.2f * ew;
        lsum.x += __expf(ex - m4.x); lsum.y += __expf(ey - m4.y);
        lsum.z += __expf(ez - m4.z); lsum.w += __expf(ew - m4.w);
    }
    red4[tid] = lsum;
    __syncthreads();
#pragma unroll
    for (int st = 128; st >= 1; st >>= 1) {
        if (tid < st) {
            float4 a = red4[tid], b = red4[tid + st];
            a.x += b.x; a.y += b.y; a.z += b.z; a.w += b.w;
            red4[tid] = a;
        }
        __syncthreads();
    }
    if (tid == 0) {
        float4 d = red4[0];
        invd_sh[0] = 1.f / d.x; invd_sh[1] = 1.f / d.y;
        invd_sh[2] = 1.f / d.z; invd_sh[3] = 1.f / d.w;
    }
    __syncthreads();
    const float4 iv4 = make_float4(invd_sh[0], invd_sh[1], invd_sh[2], invd_sh[3]);

    // ---- pass 3: chunked weighted gather (alpha computed ONCE per edge/head) ----
    float acc = 0.f;
    for (int ch = beg; ch < end; ch += 64) {
        int cl = end - ch; if (cl > 64) cl = 64;
        __syncthreads();   // protect previous chunk's s_sh / al_sh reads
        if (tid < cl) {
            int s = g_csr[ch + tid];
            s_sh[tid] = s;
            float4 as = *(const float4*)&g_asrc[s * NHEAD];
            float ex = as.x + ad4.x; ex = ex >= 0.f ? ex : 0.2f * ex;
            float ey = as.y + ad4.y; ey = ey >= 0.f ? ey : 0.2f * ey;
            float ez = as.z + ad4.z; ez = ez >= 0.f ? ez : 0.2f * ez;
            float ew = as.w + ad4.w; ew = ew >= 0.f ? ew : 0.2f * ew;
            al_sh[0][tid] = __expf(ex - m4.x) * iv4.x;
            al_sh[1][tid] = __expf(ey - m4.y) * iv4.y;
            al_sh[2][tid] = __expf(ez - m4.z) * iv4.z;
            al_sh[3][tid] = __expf(ew - m4.w) * iv4.w;
        }
        __syncthreads();
#pragma unroll 4
        for (int jj = 0; jj < cl; jj++) {
            int s = s_sh[jj];
            acc += g_h[(long long)s * FEAT + tid] * al_sh[head][jj];
        }
    }

    // ---- epilogue: bias, relu, L2-normalize over 256 channels ----
    float v = fmaxf(acc + bias[tid], 0.f);
    red[tid] = v * v;
    __syncthreads();
#pragma unroll
    for (int st = 128; st >= 1; st >>= 1) {
        if (tid < st) red[tid] += red[tid + st];
        __syncthreads();
    }
    float norm = sqrtf(red[0]);
    float scale = 1.f / fmaxf(norm, 1e-12f);
    out[(long long)n * FEAT + tid] = v * scale;
}

// ---------------- launch ----------------
extern "C" void kernel_launch(void* const* d_in, const int* in_sizes, int n_in,
                              void* d_out, int out_size) {
    const float* x       = (const float*)d_in[0];
    const int*   ei      = (const int*)  d_in[1];
    const float* W       = (const float*)d_in[2];
    // d_in[3] = att_src, d_in[4] = att_dst, d_in[5] = bias
    const float* att_src = (const float*)d_in[3];
    const float* att_dst = (const float*)d_in[4];
    const float* bias    = (const float*)d_in[5];
    float* out = (float*)d_out;

    const int N = in_sizes[0] / FEAT;
    const int E = in_sizes[1] / 2;
    const int tot = E + N;

    zero_kernel<<<(N + 256) / 256, 256>>>(N);

    dim3 ggrid(FEAT / 128, (N + 127) / 128);
    gemm_kernel<<<ggrid, 256>>>(x, W, N);

    logits_kernel<<<N, 256>>>(att_src, att_dst, N);

    count_kernel<<<(tot + 255) / 256, 256>>>(ei, E, N);
    scan_kernel<<<1, 1024>>>(N);
    scatter_kernel<<<(tot + 255) / 256, 256>>>(ei, E, N);

    aggregate_kernel<<<N, 256>>>(bias, out, N);
}

// round 2
// speedup vs baseline: 1.2038x; 1.2038x over previous
#include <cuda_runtime.h>

// ---------------- problem constants / scratch ----------------
#define NMAX 50000
#define EMAX 1600000
#define FEAT 256
#define NHEAD 4

__device__ __align__(16) float g_h[(long long)NMAX * FEAT];   // 51.2 MB: h = x@W
__device__ __align__(16) float g_asrc[NMAX * NHEAD];
__device__ __align__(16) float g_adst[NMAX * NHEAD];
__device__ unsigned g_m[NMAX * NHEAD];                        // encoded per-(dst,head) max
__device__ __align__(16) float g_den[NMAX * NHEAD];           // softmax denominators
__device__ int   g_cnt[NMAX + 1];
__device__ int   g_off[NMAX + 2];
__device__ int   g_cur[NMAX + 1];
__device__ int   g_csr[EMAX + NMAX];                          // src node per dst-grouped slot
__device__ __align__(16) float g_num[(long long)(EMAX + NMAX) * NHEAD]; // exp(e-m) per slot

// order-preserving float<->uint encoding for atomicMax
__device__ __forceinline__ unsigned fenc(float f) {
    int i = __float_as_int(f);
    return (i >= 0) ? ((unsigned)i | 0x80000000u) : ~(unsigned)i;
}
__device__ __forceinline__ float fdec(unsigned u) {
    return (u & 0x80000000u) ? __int_as_float((int)(u & 0x7fffffffu))
                             : __int_as_float(~(int)u);
}

// ---------------- 0: zero counters / max / den ----------------
__global__ void zero_kernel(int N) {
    int i = blockIdx.x * blockDim.x + threadIdx.x;
    if (i < N * NHEAD) { g_m[i] = 0u; g_den[i] = 0.f; }
    if (i <= N) g_cnt[i] = 0;
}

// ---------------- 1: SGEMM  g_h = x @ W  (K = N = 256) ----------------
__global__ void gemm_kernel(const float* __restrict__ A, const float* __restrict__ B, int M) {
    constexpr int K = 256, NN = 256;
    constexpr int BM = 128, BN = 128, BK = 8, TM = 8, TN = 8;
    __shared__ __align__(16) float As[BK][BM];
    __shared__ __align__(16) float Bs[BK][BN];
    const int tid = threadIdx.x;
    const int tx = tid % (BN / TN);
    const int ty = tid / (BN / TN);
    const int row0 = blockIdx.y * BM;
    const int col0 = blockIdx.x * BN;

    const int a_r = tid >> 1;
    const int a_c = (tid & 1) * 4;
    const int b_r = tid >> 5;
    const int b_c = (tid & 31) * 4;

    float acc[TM][TN];
#pragma unroll
    for (int i = 0; i < TM; i++)
#pragma unroll
        for (int j = 0; j < TN; j++) acc[i][j] = 0.f;

    for (int k0 = 0; k0 < K; k0 += BK) {
        float4 av = make_float4(0.f, 0.f, 0.f, 0.f);
        int ar = row0 + a_r;
        if (ar < M) av = *(const float4*)&A[(long long)ar * K + k0 + a_c];
        As[a_c + 0][a_r] = av.x;
        As[a_c + 1][a_r] = av.y;
        As[a_c + 2][a_r] = av.z;
        As[a_c + 3][a_r] = av.w;
        *(float4*)&Bs[b_r][b_c] = *(const float4*)&B[(k0 + b_r) * NN + col0 + b_c];
        __syncthreads();
#pragma unroll
        for (int kk = 0; kk < BK; kk++) {
            float ra[TM], rb[TN];
            *(float4*)&ra[0] = *(const float4*)&As[kk][ty * TM];
            *(float4*)&ra[4] = *(const float4*)&As[kk][ty * TM + 4];
            *(float4*)&rb[0] = *(const float4*)&Bs[kk][tx * TN];
            *(float4*)&rb[4] = *(const float4*)&Bs[kk][tx * TN + 4];
#pragma unroll
            for (int i = 0; i < TM; i++)
#pragma unroll
                for (int j = 0; j < TN; j++) acc[i][j] += ra[i] * rb[j];
        }
        __syncthreads();
    }
#pragma unroll
    for (int i = 0; i < TM; i++) {
        int r = row0 + ty * TM + i;
        if (r < M) {
            *(float4*)&g_h[(long long)r * FEAT + col0 + tx * TN]     = *(float4*)&acc[i][0];
            *(float4*)&g_h[(long long)r * FEAT + col0 + tx * TN + 4] = *(float4*)&acc[i][4];
        }
    }
}

// ---------------- 2: per-node attention logits ----------------
__global__ void logits_kernel(const float* __restrict__ att_src,
                              const float* __restrict__ att_dst, int N) {
    const int n = blockIdx.x;
    const int tid = threadIdx.x;  // 256
    const int lane = tid & 63;
    float hv = g_h[(long long)n * FEAT + tid];
    __shared__ float s1[256], s2[256];
    s1[tid] = hv * att_src[tid];
    s2[tid] = hv * att_dst[tid];
    __syncthreads();
#pragma unroll
    for (int st = 32; st >= 1; st >>= 1) {
        if (lane < st) { s1[tid] += s1[tid + st]; s2[tid] += s2[tid + st]; }
        __syncthreads();
    }
    if (lane == 0) {
        int head = tid >> 6;
        g_asrc[n * NHEAD + head] = s1[tid];
        g_adst[n * NHEAD + head] = s2[tid];
    }
}

// ---------------- 3: edge pass A — per-(dst,head) max + dst histogram ----------------
__global__ void edgeA_kernel(const int* __restrict__ ei, int E, int N) {
    int i = blockIdx.x * blockDim.x + threadIdx.x;
    if (i >= E + N) return;
    int src, dst;
    if (i < E) { src = ei[i]; dst = ei[E + i]; }
    else       { src = dst = i - E; }
    float4 as = *(const float4*)&g_asrc[src * NHEAD];
    float4 ad = *(const float4*)&g_adst[dst * NHEAD];
    float e0 = as.x + ad.x; e0 = e0 >= 0.f ? e0 : 0.2f * e0;
    float e1 = as.y + ad.y; e1 = e1 >= 0.f ? e1 : 0.2f * e1;
    float e2 = as.z + ad.z; e2 = e2 >= 0.f ? e2 : 0.2f * e2;
    float e3 = as.w + ad.w; e3 = e3 >= 0.f ? e3 : 0.2f * e3;
    atomicMax(&g_m[dst * NHEAD + 0], fenc(e0));
    atomicMax(&g_m[dst * NHEAD + 1], fenc(e1));
    atomicMax(&g_m[dst * NHEAD + 2], fenc(e2));
    atomicMax(&g_m[dst * NHEAD + 3], fenc(e3));
    atomicAdd(&g_cnt[dst], 1);
}

// ---------------- 4: single-block exclusive scan ----------------
__global__ void scan_kernel(int N) {
    __shared__ int sm[1024];
    __shared__ int carry;
    const int tid = threadIdx.x;
    if (tid == 0) carry = 0;
    __syncthreads();
    for (int base = 0; base < N; base += 1024) {
        int i = base + tid;
        int v = (i < N) ? g_cnt[i] : 0;
        sm[tid] = v;
        __syncthreads();
        for (int s = 1; s < 1024; s <<= 1) {
            int t = (tid >= s) ? sm[tid - s] : 0;
            __syncthreads();
            sm[tid] += t;
            __syncthreads();
        }
        int excl = sm[tid] - v + carry;
        if (i < N) { g_off[i] = excl; g_cur[i] = excl; }
        __syncthreads();
        if (tid == 1023) carry += sm[1023];
        __syncthreads();
    }
    if (tid == 0) g_off[N] = carry;
}

// ---------------- 5: edge pass B — scatter + exp numerators + denominators ----------------
__global__ void edgeB_kernel(const int* __restrict__ ei, int E, int N) {
    int i = blockIdx.x * blockDim.x + threadIdx.x;
    if (i >= E + N) return;
    int src, dst;
    if (i < E) { src = ei[i]; dst = ei[E + i]; }
    else       { src = dst = i - E; }
    float4 as = *(const float4*)&g_asrc[src * NHEAD];
    float4 ad = *(const float4*)&g_adst[dst * NHEAD];
    float e0 = as.x + ad.x; e0 = e0 >= 0.f ? e0 : 0.2f * e0;
    float e1 = as.y + ad.y; e1 = e1 >= 0.f ? e1 : 0.2f * e1;
    float e2 = as.z + ad.z; e2 = e2 >= 0.f ? e2 : 0.2f * e2;
    float e3 = as.w + ad.w; e3 = e3 >= 0.f ? e3 : 0.2f * e3;
    float n0 = __expf(e0 - fdec(g_m[dst * NHEAD + 0]));
    float n1 = __expf(e1 - fdec(g_m[dst * NHEAD + 1]));
    float n2 = __expf(e2 - fdec(g_m[dst * NHEAD + 2]));
    float n3 = __expf(e3 - fdec(g_m[dst * NHEAD + 3]));
    int slot = atomicAdd(&g_cur[dst], 1);
    g_csr[slot] = src;
    *(float4*)&g_num[(long long)slot * NHEAD] = make_float4(n0, n1, n2, n3);
    atomicAdd(&g_den[dst * NHEAD + 0], n0);
    atomicAdd(&g_den[dst * NHEAD + 1], n1);
    atomicAdd(&g_den[dst * NHEAD + 2], n2);
    atomicAdd(&g_den[dst * NHEAD + 3], n3);
}

// ---------------- 6: weighted gather + relu + L2 norm ----------------
// 256 threads = 4 edge-groups x 64 threads; thread t of a group owns channels [4t,4t+4)
__global__ void aggregate_kernel(const float* __restrict__ bias,
                                 float* __restrict__ out, int N) {
    const int n   = blockIdx.x;
    const int tid = threadIdx.x;
    const int g   = tid >> 6;       // edge group 0..3
    const int t   = tid & 63;       // channel-quad index
    const int c0  = t * 4;          // first channel
    const int head = t >> 4;        // c0/64

    __shared__ float invd[4];
    __shared__ int   s_sh[256];
    __shared__ float al_sh[256][4];
    __shared__ __align__(16) float4 part[4][64];
    __shared__ float wsum[2];

    const int beg = g_off[n];
    const int end = g_off[n + 1];
    if (tid < 4) invd[tid] = 1.f / g_den[n * NHEAD + tid];
    __syncthreads();
    const float4 iv = make_float4(invd[0], invd[1], invd[2], invd[3]);

    float4 acc = make_float4(0.f, 0.f, 0.f, 0.f);
    for (int ch = beg; ch < end; ch += 256) {
        int cl = end - ch; if (cl > 256) cl = 256;
        __syncthreads();
        if (tid < cl) {
            int s = g_csr[ch + tid];
            s_sh[tid] = s;
            float4 nm = *(const float4*)&g_num[(long long)(ch + tid) * NHEAD];
            al_sh[tid][0] = nm.x * iv.x;
            al_sh[tid][1] = nm.y * iv.y;
            al_sh[tid][2] = nm.z * iv.z;
            al_sh[tid][3] = nm.w * iv.w;
        }
        __syncthreads();
        for (int jj = g; jj < cl; jj += 4) {
            int s = s_sh[jj];
            float a = al_sh[jj][head];
            float4 hv = *(const float4*)&g_h[(long long)s * FEAT + c0];
            acc.x += hv.x * a;
            acc.y += hv.y * a;
            acc.z += hv.z * a;
            acc.w += hv.w * a;
        }
    }
    part[g][t] = acc;
    __syncthreads();

    float4 v;
    if (tid < 64) {
        float4 a = part[0][t], b = part[1][t], c = part[2][t], d = part[3][t];
        float4 b4 = *(const float4*)&bias[c0];
        v.x = fmaxf(a.x + b.x + c.x + d.x + b4.x, 0.f);
        v.y = fmaxf(a.y + b.y + c.y + d.y + b4.y, 0.f);
        v.z = fmaxf(a.z + b.z + c.z + d.z + b4.z, 0.f);
        v.w = fmaxf(a.w + b.w + c.w + d.w + b4.w, 0.f);
        float sq = v.x * v.x + v.y * v.y + v.z * v.z + v.w * v.w;
#pragma unroll
        for (int st = 16; st >= 1; st >>= 1)
            sq += __shfl_xor_sync(0xffffffff, sq, st);
        if ((t & 31) == 0) wsum[t >> 5] = sq;
    }
    __syncthreads();
    if (tid < 64) {
        float norm = sqrtf(wsum[0] + wsum[1]);
        float sc = 1.f / fmaxf(norm, 1e-12f);
        v.x *= sc; v.y *= sc; v.z *= sc; v.w *= sc;
        *(float4*)&out[(long long)n * FEAT + c0] = v;
    }
}

// ---------------- launch ----------------
extern "C" void kernel_launch(void* const* d_in, const int* in_sizes, int n_in,
                              void* d_out, int out_size) {
    const float* x       = (const float*)d_in[0];
    const int*   ei      = (const int*)  d_in[1];
    const float* W       = (const float*)d_in[2];
    const float* att_src = (const float*)d_in[3];
    const float* att_dst = (const float*)d_in[4];
    const float* bias    = (const float*)d_in[5];
    float* out = (float*)d_out;

    const int N = in_sizes[0] / FEAT;
    const int E = in_sizes[1] / 2;
    const int tot = E + N;

    zero_kernel<<<(N * NHEAD + 256) / 256, 256>>>(N);

    dim3 ggrid(FEAT / 128, (N + 127) / 128);
    gemm_kernel<<<ggrid, 256>>>(x, W, N);

    logits_kernel<<<N, 256>>>(att_src, att_dst, N);

    edgeA_kernel<<<(tot + 255) / 256, 256>>>(ei, E, N);
    scan_kernel<<<1, 1024>>>(N);
    edgeB_kernel<<<(tot + 255) / 256, 256>>>(ei, E, N);

    aggregate_kernel<<<N, 256>>>(bias, out, N);
}

// round 4
// speedup vs baseline: 1.3897x; 1.1545x over previous
#include <cuda_runtime.h>
#include <cstdint>

// ---------------- problem constants / scratch ----------------
#define NMAX 50000
#define EMAX 1600000
#define FEAT 256
#define NHEAD 4

__device__ __align__(16) float g_h[(long long)NMAX * FEAT];   // 51.2 MB: h = x@W
__device__ __align__(16) float g_asrc[NMAX * NHEAD];
__device__ __align__(16) float g_adst[NMAX * NHEAD];
__device__ __align__(16) float g_inv[NMAX * NHEAD];           // 1/den per (dst,head)
__device__ int   g_cnt[NMAX + 1];
__device__ int   g_off[NMAX + 2];
__device__ int   g_cur[NMAX + 1];
__device__ int   g_csr[EMAX + NMAX];                          // src per dst-grouped slot
__device__ __align__(16) float g_num[(long long)(EMAX + NMAX) * NHEAD]; // e4 then exp(e-m)

// ---------------- 0: zero counters ----------------
__global__ void zero_kernel(int N) {
    int i = blockIdx.x * blockDim.x + threadIdx.x;
    if (i <= N) g_cnt[i] = 0;
}

// ---------------- 1: tf32 split-3 MMA GEMM  g_h = x @ W ----------------
// tf32 cvt: destination must be a b32 register in PTX
__device__ __forceinline__ uint32_t tf32_rna_bits(float x) {
    uint32_t r;
    asm("cvt.rna.tf32.f32 %0, %1;" : "=r"(r) : "f"(x));
    return r;
}
// split x into hi (tf32-representable, as float) and lo (residual)
__device__ __forceinline__ void tf32_split(float x, float& hi, float& lo) {
    hi = __uint_as_float(tf32_rna_bits(x));
    lo = x - hi;
}
__device__ __forceinline__ void mma8(float* d, const uint32_t* a, uint32_t b0, uint32_t b1) {
    asm volatile("mma.sync.aligned.m16n8k8.row.col.f32.tf32.tf32.f32 "
                 "{%0,%1,%2,%3}, {%4,%5,%6,%7}, {%8,%9}, {%0,%1,%2,%3};"
                 : "+f"(d[0]), "+f"(d[1]), "+f"(d[2]), "+f"(d[3])
                 : "r"(a[0]), "r"(a[1]), "r"(a[2]), "r"(a[3]), "r"(b0), "r"(b1));
}

#define LDA 36
#define LDB 136
#define A_PLANE (128 * LDA)          // 4608 floats
#define B_PLANE (32 * LDB)           // 4352 floats
#define STAGE_FLOATS (2 * A_PLANE + 2 * B_PLANE)   // 17920
#define GEMM_SMEM_BYTES (2 * STAGE_FLOATS * 4)     // 143360

__global__ void __launch_bounds__(256, 1)
gemm_tf32_kernel(const float* __restrict__ A, const float* __restrict__ B, int M) {
    extern __shared__ float S[];
    const int tid = threadIdx.x;
    const int wid = tid >> 5, lane = tid & 31;
    const int warp_m = wid & 3;      // 0..3 -> 32 rows each
    const int warp_n = wid >> 2;     // 0..1 -> 64 cols each
    const int gid = lane >> 2, tig = lane & 3;
    const int row0 = blockIdx.y * 128;
    const int col0 = blockIdx.x * 128;

    // global load assignment
    const int ar = tid >> 1;          // 0..127
    const int ac = (tid & 1) * 16;    // 0 or 16
    const int br = tid >> 3;          // 0..31
    const int bc = (tid & 7) * 16;    // 0..112

    float acc[2][8][4];
#pragma unroll
    for (int i = 0; i < 2; i++)
#pragma unroll
        for (int j = 0; j < 8; j++)
#pragma unroll
            for (int q = 0; q < 4; q++) acc[i][j][q] = 0.f;

    float4 va[4], vb[4];
    const int arow = row0 + ar;

    // ---- load chunk 0 ----
#pragma unroll
    for (int q = 0; q < 4; q++) {
        va[q] = (arow < M) ? *(const float4*)&A[(size_t)arow * 256 + ac + q * 4]
                           : make_float4(0.f, 0.f, 0.f, 0.f);
        vb[q] = *(const float4*)&B[(size_t)br * 256 + col0 + bc + q * 4];
    }
    // ---- stash chunk 0 into stage 0 ----
    {
        float* Ah = S;
        float* Al = S + A_PLANE;
        float* Bh = S + 2 * A_PLANE;
        float* Bl = Bh + B_PLANE;
#pragma unroll
        for (int q = 0; q < 4; q++) {
            float4 h4, l4;
            tf32_split(va[q].x, h4.x, l4.x);
            tf32_split(va[q].y, h4.y, l4.y);
            tf32_split(va[q].z, h4.z, l4.z);
            tf32_split(va[q].w, h4.w, l4.w);
            *(float4*)&Ah[ar * LDA + ac + q * 4] = h4;
            *(float4*)&Al[ar * LDA + ac + q * 4] = l4;
            tf32_split(vb[q].x, h4.x, l4.x);
            tf32_split(vb[q].y, h4.y, l4.y);
            tf32_split(vb[q].z, h4.z, l4.z);
            tf32_split(vb[q].w, h4.w, l4.w);
            *(float4*)&Bh[br * LDB + bc + q * 4] = h4;
            *(float4*)&Bl[br * LDB + bc + q * 4] = l4;
        }
    }
    __syncthreads();

    for (int c = 0; c < 8; c++) {
        // prefetch next chunk to registers
        if (c < 7) {
            const int k0 = (c + 1) * 32;
#pragma unroll
            for (int q = 0; q < 4; q++) {
                va[q] = (arow < M) ? *(const float4*)&A[(size_t)arow * 256 + k0 + ac + q * 4]
                                   : make_float4(0.f, 0.f, 0.f, 0.f);
                vb[q] = *(const float4*)&B[(size_t)(k0 + br) * 256 + col0 + bc + q * 4];
            }
        }
        // compute from stage c&1
        {
            const float* Ah = S + (c & 1) * STAGE_FLOATS;
            const float* Al = Ah + A_PLANE;
            const float* Bh = Ah + 2 * A_PLANE;
            const float* Bl = Bh + B_PLANE;
#pragma unroll
            for (int ks = 0; ks < 4; ks++) {
                const int k8 = ks * 8;
                uint32_t ahf[2][4], alf[2][4];
#pragma unroll
                for (int i = 0; i < 2; i++) {
                    int mr = warp_m * 32 + i * 16 + gid;
                    ahf[i][0] = __float_as_uint(Ah[mr * LDA + k8 + tig]);
                    ahf[i][1] = __float_as_uint(Ah[(mr + 8) * LDA + k8 + tig]);
                    ahf[i][2] = __float_as_uint(Ah[mr * LDA + k8 + tig + 4]);
                    ahf[i][3] = __float_as_uint(Ah[(mr + 8) * LDA + k8 + tig + 4]);
                    alf[i][0] = __float_as_uint(Al[mr * LDA + k8 + tig]);
                    alf[i][1] = __float_as_uint(Al[(mr + 8) * LDA + k8 + tig]);
                    alf[i][2] = __float_as_uint(Al[mr * LDA + k8 + tig + 4]);
                    alf[i][3] = __float_as_uint(Al[(mr + 8) * LDA + k8 + tig + 4]);
                }
#pragma unroll
                for (int j = 0; j < 8; j++) {
                    int nb = warp_n * 64 + j * 8 + gid;
                    uint32_t bh0 = __float_as_uint(Bh[(k8 + tig) * LDB + nb]);
                    uint32_t bh1 = __float_as_uint(Bh[(k8 + tig + 4) * LDB + nb]);
                    uint32_t bl0 = __float_as_uint(Bl[(k8 + tig) * LDB + nb]);
                    uint32_t bl1 = __float_as_uint(Bl[(k8 + tig + 4) * LDB + nb]);
#pragma unroll
                    for (int i = 0; i < 2; i++) {
                        mma8(acc[i][j], alf[i], bh0, bh1);   // lo*hi
                        mma8(acc[i][j], ahf[i], bl0, bl1);   // hi*lo
                        mma8(acc[i][j], ahf[i], bh0, bh1);   // hi*hi
                    }
                }
            }
        }
        // stash prefetched chunk to the other stage
        if (c < 7) {
            float* Ah = S + ((c + 1) & 1) * STAGE_FLOATS;
            float* Al = Ah + A_PLANE;
            float* Bh = Ah + 2 * A_PLANE;
            float* Bl = Bh + B_PLANE;
#pragma unroll
            for (int q = 0; q < 4; q++) {
                float4 h4, l4;
                tf32_split(va[q].x, h4.x, l4.x);
                tf32_split(va[q].y, h4.y, l4.y);
                tf32_split(va[q].z, h4.z, l4.z);
                tf32_split(va[q].w, h4.w, l4.w);
                *(float4*)&Ah[ar * LDA + ac + q * 4] = h4;
                *(float4*)&Al[ar * LDA + ac + q * 4] = l4;
                tf32_split(vb[q].x, h4.x, l4.x);
                tf32_split(vb[q].y, h4.y, l4.y);
                tf32_split(vb[q].z, h4.z, l4.z);
                tf32_split(vb[q].w, h4.w, l4.w);
                *(float4*)&Bh[br * LDB + bc + q * 4] = h4;
                *(float4*)&Bl[br * LDB + bc + q * 4] = l4;
            }
        }
        __syncthreads();
    }

    // ---- epilogue: write to g_h ----
#pragma unroll
    for (int i = 0; i < 2; i++) {
        int r0 = row0 + warp_m * 32 + i * 16 + gid;
#pragma unroll
        for (int j = 0; j < 8; j++) {
            int cc = col0 + warp_n * 64 + j * 8 + tig * 2;
            if (r0 < M)
                *(float2*)&g_h[(size_t)r0 * 256 + cc] = make_float2(acc[i][j][0], acc[i][j][1]);
            if (r0 + 8 < M)
                *(float2*)&g_h[(size_t)(r0 + 8) * 256 + cc] = make_float2(acc[i][j][2], acc[i][j][3]);
        }
    }
}

// ---------------- 2: per-node attention logits ----------------
__global__ void logits_kernel(const float* __restrict__ att_src,
                              const float* __restrict__ att_dst, int N) {
    const int n = blockIdx.x;
    const int tid = threadIdx.x;  // 256
    const int lane = tid & 63;
    float hv = g_h[(long long)n * FEAT + tid];
    __shared__ float s1[256], s2[256];
    s1[tid] = hv * att_src[tid];
    s2[tid] = hv * att_dst[tid];
    __syncthreads();
#pragma unroll
    for (int st = 32; st >= 1; st >>= 1) {
        if (lane < st) { s1[tid] += s1[tid + st]; s2[tid] += s2[tid + st]; }
        __syncthreads();
    }
    if (lane == 0) {
        int head = tid >> 6;
        g_asrc[n * NHEAD + head] = s1[tid];
        g_adst[n * NHEAD + head] = s2[tid];
    }
}

// ---------------- 3: dst histogram (1 atomic/edge) ----------------
__global__ void count_kernel(const int* __restrict__ ei, int E, int N) {
    int i = blockIdx.x * blockDim.x + threadIdx.x;
    if (i >= E + N) return;
    int dst = (i < E) ? ei[E + i] : (i - E);
    atomicAdd(&g_cnt[dst], 1);
}

// ---------------- 4: single-block exclusive scan ----------------
__global__ void scan_kernel(int N) {
    __shared__ int sm[1024];
    __shared__ int carry;
    const int tid = threadIdx.x;
    if (tid == 0) carry = 0;
    __syncthreads();
    for (int base = 0; base < N; base += 1024) {
        int i = base + tid;
        int v = (i < N) ? g_cnt[i] : 0;
        sm[tid] = v;
        __syncthreads();
        for (int s = 1; s < 1024; s <<= 1) {
            int t = (tid >= s) ? sm[tid - s] : 0;
            __syncthreads();
            sm[tid] += t;
            __syncthreads();
        }
        int excl = sm[tid] - v + carry;
        if (i < N) { g_off[i] = excl; g_cur[i] = excl; }
        __syncthreads();
        if (tid == 1023) carry += sm[1023];
        __syncthreads();
    }
    if (tid == 0) g_off[N] = carry;
}

// ---------------- 5: scatter edges + raw leaky logits ----------------
__global__ void scatter_kernel(const int* __restrict__ ei, int E, int N) {
    int i = blockIdx.x * blockDim.x + threadIdx.x;
    if (i >= E + N) return;
    int src, dst;
    if (i < E) { src = ei[i]; dst = ei[E + i]; }
    else       { src = dst = i - E; }
    float4 as = *(const float4*)&g_asrc[src * NHEAD];
    float4 ad = *(const float4*)&g_adst[dst * NHEAD];
    float e0 = as.x + ad.x; e0 = e0 >= 0.f ? e0 : 0.2f * e0;
    float e1 = as.y + ad.y; e1 = e1 >= 0.f ? e1 : 0.2f * e1;
    float e2 = as.z + ad.z; e2 = e2 >= 0.f ? e2 : 0.2f * e2;
    float e3 = as.w + ad.w; e3 = e3 >= 0.f ? e3 : 0.2f * e3;
    int slot = atomicAdd(&g_cur[dst], 1);
    g_csr[slot] = src;
    *(float4*)&g_num[(long long)slot * NHEAD] = make_float4(e0, e1, e2, e3);
}

// ---------------- 6: segmented softmax stats (warp per dst, no atomics) ----------------
__global__ void stats_kernel(int N) {
    int w = (blockIdx.x * blockDim.x + threadIdx.x) >> 5;
    int lane = threadIdx.x & 31;
    if (w >= N) return;
    const int beg = g_off[w];
    const int end = g_off[w + 1];
    float4 m = make_float4(-1e30f, -1e30f, -1e30f, -1e30f);
    for (int i = beg + lane; i < end; i += 32) {
        float4 e = *(const float4*)&g_num[(long long)i * NHEAD];
        m.x = fmaxf(m.x, e.x); m.y = fmaxf(m.y, e.y);
        m.z = fmaxf(m.z, e.z); m.w = fmaxf(m.w, e.w);
    }
#pragma unroll
    for (int st = 16; st >= 1; st >>= 1) {
        m.x = fmaxf(m.x, __shfl_xor_sync(0xffffffff, m.x, st));
        m.y = fmaxf(m.y, __shfl_xor_sync(0xffffffff, m.y, st));
        m.z = fmaxf(m.z, __shfl_xor_sync(0xffffffff, m.z, st));
        m.w = fmaxf(m.w, __shfl_xor_sync(0xffffffff, m.w, st));
    }
    float4 den = make_float4(0.f, 0.f, 0.f, 0.f);
    for (int i = beg + lane; i < end; i += 32) {
        float4 e = *(const float4*)&g_num[(long long)i * NHEAD];
        e.x = __expf(e.x - m.x); e.y = __expf(e.y - m.y);
        e.z = __expf(e.z - m.z); e.w = __expf(e.w - m.w);
        *(float4*)&g_num[(long long)i * NHEAD] = e;
        den.x += e.x; den.y += e.y; den.z += e.z; den.w += e.w;
    }
#pragma unroll
    for (int st = 16; st >= 1; st >>= 1) {
        den.x += __shfl_xor_sync(0xffffffff, den.x, st);
        den.y += __shfl_xor_sync(0xffffffff, den.y, st);
        den.z += __shfl_xor_sync(0xffffffff, den.z, st);
        den.w += __shfl_xor_sync(0xffffffff, den.w, st);
    }
    if (lane == 0) {
        *(float4*)&g_inv[w * NHEAD] =
            make_float4(1.f / den.x, 1.f / den.y, 1.f / den.z, 1.f / den.w);
    }
}

// ---------------- 7: weighted gather + relu + L2 norm ----------------
__global__ void aggregate_kernel(const float* __restrict__ bias,
                                 float* __restrict__ out, int N) {
    const int n   = blockIdx.x;
    const int tid = threadIdx.x;
    const int g   = tid >> 6;       // edge group 0..3
    const int t   = tid & 63;       // channel-quad index
    const int c0  = t * 4;
    const int head = t >> 4;

    __shared__ float invd[4];
    __shared__ int   s_sh[256];
    __shared__ float al_sh[256][4];
    __shared__ __align__(16) float4 part[4][64];
    __shared__ float wsum[2];

    const int beg = g_off[n];
    const int end = g_off[n + 1];
    if (tid < 4) invd[tid] = g_inv[n * NHEAD + tid];
    __syncthreads();
    const float4 iv = make_float4(invd[0], invd[1], invd[2], invd[3]);

    float4 acc = make_float4(0.f, 0.f, 0.f, 0.f);
    for (int ch = beg; ch < end; ch += 256) {
        int cl = end - ch; if (cl > 256) cl = 256;
        __syncthreads();
        if (tid < cl) {
            s_sh[tid] = g_csr[ch + tid];
            float4 nm = *(const float4*)&g_num[(long long)(ch + tid) * NHEAD];
            al_sh[tid][0] = nm.x * iv.x;
            al_sh[tid][1] = nm.y * iv.y;
            al_sh[tid][2] = nm.z * iv.z;
            al_sh[tid][3] = nm.w * iv.w;
        }
        __syncthreads();
        for (int jj = g; jj < cl; jj += 4) {
            int s = s_sh[jj];
            float a = al_sh[jj][head];
            float4 hv = *(const float4*)&g_h[(long long)s * FEAT + c0];
            acc.x += hv.x * a;
            acc.y += hv.y * a;
            acc.z += hv.z * a;
            acc.w += hv.w * a;
        }
    }
    part[g][t] = acc;
    __syncthreads();

    float4 v;
    if (tid < 64) {
        float4 a = part[0][t], b = part[1][t], c = part[2][t], d = part[3][t];
        float4 b4 = *(const float4*)&bias[c0];
        v.x = fmaxf(a.x + b.x + c.x + d.x + b4.x, 0.f);
        v.y = fmaxf(a.y + b.y + c.y + d.y + b4.y, 0.f);
        v.z = fmaxf(a.z + b.z + c.z + d.z + b4.z, 0.f);
        v.w = fmaxf(a.w + b.w + c.w + d.w + b4.w, 0.f);
        float sq = v.x * v.x + v.y * v.y + v.z * v.z + v.w * v.w;
#pragma unroll
        for (int st = 16; st >= 1; st >>= 1)
            sq += __shfl_xor_sync(0xffffffff, sq, st);
        if ((t & 31) == 0) wsum[t >> 5] = sq;
    }
    __syncthreads();
    if (tid < 64) {
        float norm = sqrtf(wsum[0] + wsum[1]);
        float sc = 1.f / fmaxf(norm, 1e-12f);
        v.x *= sc; v.y *= sc; v.z *= sc; v.w *= sc;
        *(float4*)&out[(long long)n * FEAT + c0] = v;
    }
}

// ---------------- launch ----------------
extern "C" void kernel_launch(void* const* d_in, const int* in_sizes, int n_in,
                              void* d_out, int out_size) {
    const float* x       = (const float*)d_in[0];
    const int*   ei      = (const int*)  d_in[1];
    const float* W       = (const float*)d_in[2];
    const float* att_src = (const float*)d_in[3];
    const float* att_dst = (const float*)d_in[4];
    const float* bias    = (const float*)d_in[5];
    float* out = (float*)d_out;

    const int N = in_sizes[0] / FEAT;
    const int E = in_sizes[1] / 2;
    const int tot = E + N;

    static bool attr_done = false;
    if (!attr_done) {
        cudaFuncSetAttribute(gemm_tf32_kernel,
                             cudaFuncAttributeMaxDynamicSharedMemorySize, GEMM_SMEM_BYTES);
        attr_done = true;
    }

    zero_kernel<<<(N + 256) / 256, 256>>>(N);

    dim3 ggrid(FEAT / 128, (N + 127) / 128);
    gemm_tf32_kernel<<<ggrid, 256, GEMM_SMEM_BYTES>>>(x, W, N);

    logits_kernel<<<N, 256>>>(att_src, att_dst, N);

    count_kernel<<<(tot + 255) / 256, 256>>>(ei, E, N);
    scan_kernel<<<1, 1024>>>(N);
    scatter_kernel<<<(tot + 255) / 256, 256>>>(ei, E, N);
    stats_kernel<<<(N * 32 + 255) / 256, 256>>>(N);

    aggregate_kernel<<<N, 256>>>(bias, out, N);
}